// round 1
// baseline (speedup 1.0000x reference)
#include <cuda_runtime.h>

// TT-linear: y = x @ W^T + bias, W from TT cores
//   c0: [1,32(o0),32(i0),4(r1)]  c1: [4(r1),16(o1),16(i1),4(r2)]  c2: [4(r2),16(o2),16(i2),1]
// y[t, o0*256+o1*16+o2] = sum_{i0,i1,i2,r1,r2} x[t, i0*256+i1*16+i2] * c0*c1*c2
//
// One CTA per token (128 CTAs), 256 threads = (o1,o2).
// Per i0: A[i1,r2,o2] (smem, double buffered) -> B[r1] (regs) -> y[32] (regs).

#define THREADS 256

__global__ __launch_bounds__(THREADS, 1)
void tt_linear_kernel(const float* __restrict__ x,
                      const float* __restrict__ g0,
                      const float* __restrict__ g1,
                      const float* __restrict__ g2,
                      const float* __restrict__ bias,
                      float* __restrict__ out)
{
    __shared__ __align__(16) float sc0[4096];    // [i0][o0][r1]
    __shared__ __align__(16) float sc1[4096];    // [o1][i1][r2][r1]
    __shared__ __align__(16) float sc2[1024];    // [i2][r2][o2]
    __shared__ __align__(16) float sA[2][1024];  // [i1][r2][o2]

    const int tid   = threadIdx.x;
    const int token = blockIdx.x;
    const int o1    = tid >> 4;    // also plays role of i1 in step 1
    const int o2    = tid & 15;
    const int lane  = tid & 31;

    // ---- cooperative core relayout into smem ----
    for (int idx = tid; idx < 4096; idx += THREADS) {
        // g0 flat = (o0*32 + i0)*4 + r1
        int r1 = idx & 3, i0 = (idx >> 2) & 31, o0 = idx >> 7;
        sc0[(i0 * 32 + o0) * 4 + r1] = g0[idx];
    }
    for (int idx = tid; idx < 4096; idx += THREADS) {
        // g1 flat = ((r1*16 + o1)*16 + i1)*4 + r2
        int r2 = idx & 3, i1 = (idx >> 2) & 15, o1g = (idx >> 6) & 15, r1 = idx >> 10;
        sc1[((o1g * 16 + i1) * 4 + r2) * 4 + r1] = g1[idx];
    }
    for (int idx = tid; idx < 1024; idx += THREADS) {
        // g2 flat = (r2*16 + o2)*16 + i2
        int i2 = idx & 15, o2g = (idx >> 4) & 15, r2 = idx >> 8;
        sc2[(i2 * 4 + r2) * 16 + o2g] = g2[idx];
    }

    const float* xrow = x + token * 8192;
    float xv = xrow[tid];          // x[i0=0 slice]: warp w's lanes hold exactly warp w's 32 values

    float y[32];
    #pragma unroll
    for (int i = 0; i < 32; i++) y[i] = 0.f;

    __syncthreads();

    const int shfl_base = lane & 16;   // which half of the warp's 32 x-values this thread's i1 uses

    for (int i0 = 0; i0 < 32; i0++) {
        float* A = sA[i0 & 1];

        // prefetch next x slice (coalesced 128B/warp), latency hidden by steps 1-3
        float xnext = 0.f;
        if (i0 < 31) xnext = xrow[(i0 + 1) * 256 + tid];

        // ---- step 1: A[i1][r2][o2] = sum_i2 x[i1,i2] * c2[r2,o2,i2], i1 = tid>>4 ----
        {
            float a0 = 0.f, a1 = 0.f, a2 = 0.f, a3 = 0.f;
            #pragma unroll
            for (int i2 = 0; i2 < 16; i2++) {
                float xs = __shfl_sync(0xffffffffu, xv, shfl_base + i2);
                const float* c = &sc2[i2 * 64 + o2];   // [i2][r2][o2], r2 stride 16
                a0 += xs * c[0];
                a1 += xs * c[16];
                a2 += xs * c[32];
                a3 += xs * c[48];
            }
            const int i1 = o1;
            A[(i1 * 4 + 0) * 16 + o2] = a0;
            A[(i1 * 4 + 1) * 16 + o2] = a1;
            A[(i1 * 4 + 2) * 16 + o2] = a2;
            A[(i1 * 4 + 3) * 16 + o2] = a3;
        }
        __syncthreads();

        // ---- step 2: B[r1] = sum_{i1,r2} A[i1,r2,o2] * c1[r1,o1,i1,r2] (regs) ----
        float b0 = 0.f, b1 = 0.f, b2 = 0.f, b3 = 0.f;
        #pragma unroll 4
        for (int i1 = 0; i1 < 16; i1++) {
            #pragma unroll
            for (int r2 = 0; r2 < 4; r2++) {
                float a = A[(i1 * 4 + r2) * 16 + o2];
                float4 c = *reinterpret_cast<const float4*>(
                    &sc1[((o1 * 16 + i1) * 4 + r2) * 4]);
                b0 += a * c.x;
                b1 += a * c.y;
                b2 += a * c.z;
                b3 += a * c.w;
            }
        }

        // ---- step 3: y[o0] += sum_r1 B[r1] * c0[o0,i0,r1] (broadcast LDS.128) ----
        const float4* c0p = reinterpret_cast<const float4*>(&sc0[i0 * 128]);
        #pragma unroll
        for (int o0 = 0; o0 < 32; o0++) {
            float4 c = c0p[o0];
            y[o0] += b0 * c.x + b1 * c.y + b2 * c.z + b3 * c.w;
        }

        xv = xnext;
    }

    // ---- epilogue: add bias, coalesced stores ----
    float* orow = out + token * 8192;
    #pragma unroll
    for (int o0 = 0; o0 < 32; o0++) {
        orow[o0 * 256 + tid] = y[o0] + bias[o0 * 256 + tid];
    }
}

extern "C" void kernel_launch(void* const* d_in, const int* in_sizes, int n_in,
                              void* d_out, int out_size)
{
    const float* x    = (const float*)d_in[0];  // [128, 8192]
    const float* g0   = (const float*)d_in[1];  // [1,32,32,4]
    const float* g1   = (const float*)d_in[2];  // [4,16,16,4]
    const float* g2   = (const float*)d_in[3];  // [4,16,16,1]
    const float* bias = (const float*)d_in[4];  // [8192]
    float* out = (float*)d_out;                 // [128, 8192]

    tt_linear_kernel<<<128, THREADS>>>(x, g0, g1, g2, bias, out);
}

// round 2
// speedup vs baseline: 1.0032x; 1.0032x over previous
#include <cuda_runtime.h>

// TT-linear: y = x @ W^T + bias
//   c0: [1,32(o0),32(i0),4(r1)]  c1: [4(r1),16(o1),16(i1),4(r2)]  c2: [4(r2),16(o2),16(i2),1]
//
// Kernel 1 (grid 256 = token x i0-half, 256 thr = (o1,o2), 2 CTAs/SM):
//   per i0: A[i1,o2,r2] (smem, dbl buf) -> B[r1] (regs) -> y[32] (regs), all via fma.rn.f32x2
//   partial y -> 8MB scratch.
// Kernel 2: out = partial0 + partial1 + bias (streaming float4).

#define THREADS 256

__device__ float g_scratch[2u * 128u * 8192u];  // 8 MB partials

typedef unsigned long long u64;

__device__ __forceinline__ u64 pk2(float lo, float hi) {
    u64 r;
    asm("mov.b64 %0, {%1, %2};" : "=l"(r) : "f"(lo), "f"(hi));
    return r;
}
__device__ __forceinline__ void unpk(u64 v, float& lo, float& hi) {
    asm("mov.b64 {%0, %1}, %2;" : "=f"(lo), "=f"(hi) : "l"(v));
}
__device__ __forceinline__ u64 fma2(u64 a, u64 b, u64 c) {
    u64 d;
    asm("fma.rn.f32x2 %0, %1, %2, %3;" : "=l"(d) : "l"(a), "l"(b), "l"(c));
    return d;
}

__global__ __launch_bounds__(THREADS, 2)
void tt_partial_kernel(const float* __restrict__ x,
                       const float* __restrict__ g0,
                       const float* __restrict__ g1,
                       const float* __restrict__ g2)
{
    __shared__ __align__(16) float sc0[4096];    // [i0][r1][o0]
    __shared__ __align__(16) float sc1[4096];    // [o1][i1][r2][r1]
    __shared__ __align__(16) float sc2[1024];    // [i2][o2][r2]
    __shared__ __align__(16) float sA[2][1024];  // [i1][o2][r2]

    const int tid   = threadIdx.x;
    const int token = blockIdx.x & 127;
    const int half  = blockIdx.x >> 7;
    const int o1    = tid >> 4;          // doubles as i1 in step 1
    const int o2    = tid & 15;
    const int lane  = tid & 31;

    // ---- core relayout into smem ----
    for (int idx = tid; idx < 4096; idx += THREADS) {
        // g0 flat = (o0*32 + i0)*4 + r1  ->  sc0[(i0*4 + r1)*32 + o0]
        int r1 = idx & 3, i0 = (idx >> 2) & 31, o0 = idx >> 7;
        sc0[(i0 * 4 + r1) * 32 + o0] = g0[idx];
    }
    for (int idx = tid; idx < 4096; idx += THREADS) {
        // g1 flat = ((r1*16 + o1)*16 + i1)*4 + r2  ->  sc1[((o1*16 + i1)*4 + r2)*4 + r1]
        int r2 = idx & 3, i1 = (idx >> 2) & 15, o1g = (idx >> 6) & 15, r1 = idx >> 10;
        sc1[((o1g * 16 + i1) * 4 + r2) * 4 + r1] = g1[idx];
    }
    for (int idx = tid; idx < 1024; idx += THREADS) {
        // g2 flat = (r2*16 + o2)*16 + i2  ->  sc2[(i2*16 + o2)*4 + r2]
        int i2 = idx & 15, o2g = (idx >> 4) & 15, r2 = idx >> 8;
        sc2[(i2 * 16 + o2g) * 4 + r2] = g2[idx];
    }

    const float* xrow = x + token * 8192;
    const int i0base = half * 16;
    float xv = xrow[i0base * 256 + tid];   // warp w's lanes hold warp w's 32 x values

    u64 yp[16];                            // y[32] as packed o0 pairs
    #pragma unroll
    for (int i = 0; i < 16; i++) yp[i] = 0ull;

    __syncthreads();

    const int shfl_base = lane & 16;

    for (int it = 0; it < 16; it++) {
        const int i0 = i0base + it;
        float* A = sA[it & 1];

        float xnext = 0.f;
        if (it < 15) xnext = xrow[(i0 + 1) * 256 + tid];

        // ---- step 1: A[i1][o2][r2] = sum_i2 x[i1,i2]*c2[r2,o2,i2]  (i1 = o1 role) ----
        {
            u64 a01 = 0ull, a23 = 0ull;
            #pragma unroll
            for (int i2 = 0; i2 < 16; i2++) {
                float xs = __shfl_sync(0xffffffffu, xv, shfl_base + i2);
                u64 xd = pk2(xs, xs);
                const ulonglong2 c = *reinterpret_cast<const ulonglong2*>(
                    &sc2[(i2 * 16 + o2) * 4]);          // (r2=0,1),(r2=2,3)
                a01 = fma2(xd, c.x, a01);
                a23 = fma2(xd, c.y, a23);
            }
            ulonglong2 st;
            st.x = a01; st.y = a23;
            *reinterpret_cast<ulonglong2*>(&A[(o1 * 16 + o2) * 4]) = st;
        }
        __syncthreads();

        // ---- step 2: B[r1] = sum_{i1,r2} A[i1,o2,r2] * c1[r1,o1,i1,r2]  (packed over r1) ----
        u64 b01 = 0ull, b23 = 0ull;
        #pragma unroll
        for (int i1 = 0; i1 < 16; i1++) {
            const ulonglong2 av = *reinterpret_cast<const ulonglong2*>(
                &A[(i1 * 16 + o2) * 4]);
            float a0, a1, a2, a3;
            unpk(av.x, a0, a1);
            unpk(av.y, a2, a3);
            const ulonglong2* c1p = reinterpret_cast<const ulonglong2*>(
                &sc1[(o1 * 16 + i1) * 16]);             // [r2][(r1 0,1),(r1 2,3)]
            u64 d;
            d = pk2(a0, a0); b01 = fma2(d, c1p[0].x, b01); b23 = fma2(d, c1p[0].y, b23);
            d = pk2(a1, a1); b01 = fma2(d, c1p[1].x, b01); b23 = fma2(d, c1p[1].y, b23);
            d = pk2(a2, a2); b01 = fma2(d, c1p[2].x, b01); b23 = fma2(d, c1p[2].y, b23);
            d = pk2(a3, a3); b01 = fma2(d, c1p[3].x, b01); b23 = fma2(d, c1p[3].y, b23);
        }

        // ---- step 3: y[o0] += sum_r1 B[r1]*c0[i0,r1,o0]  (packed over o0 pairs) ----
        {
            float b0, b1, b2, b3;
            unpk(b01, b0, b1);
            unpk(b23, b2, b3);
            u64 bd[4];
            bd[0] = pk2(b0, b0); bd[1] = pk2(b1, b1);
            bd[2] = pk2(b2, b2); bd[3] = pk2(b3, b3);
            #pragma unroll
            for (int q = 0; q < 8; q++) {
                #pragma unroll
                for (int r1 = 0; r1 < 4; r1++) {
                    const ulonglong2 c = *reinterpret_cast<const ulonglong2*>(
                        &sc0[i0 * 128 + r1 * 32 + q * 4]);   // o0 = 4q..4q+3
                    yp[2 * q]     = fma2(bd[r1], c.x, yp[2 * q]);
                    yp[2 * q + 1] = fma2(bd[r1], c.y, yp[2 * q + 1]);
                }
            }
        }

        xv = xnext;
    }

    // ---- write partial (coalesced across threads) ----
    float* sp = g_scratch + ((size_t)(half * 128 + token) << 13);
    #pragma unroll
    for (int q = 0; q < 8; q++) {
        float f0, f1, f2, f3;
        unpk(yp[2 * q],     f0, f1);
        unpk(yp[2 * q + 1], f2, f3);
        sp[(4 * q + 0) * 256 + tid] = f0;
        sp[(4 * q + 1) * 256 + tid] = f1;
        sp[(4 * q + 2) * 256 + tid] = f2;
        sp[(4 * q + 3) * 256 + tid] = f3;
    }
}

__global__ __launch_bounds__(256)
void tt_reduce_kernel(const float* __restrict__ bias, float* __restrict__ out)
{
    const int idx = blockIdx.x * 256 + threadIdx.x;     // 262144 float4s
    const float4* s0 = reinterpret_cast<const float4*>(g_scratch);
    const float4* s1 = s0 + (1u << 18);                 // second half: 1048576 floats
    const float4  a  = s0[idx];
    const float4  b  = s1[idx];
    const float4  bb = *reinterpret_cast<const float4*>(&bias[(idx * 4) & 8191]);
    float4 r;
    r.x = a.x + b.x + bb.x;
    r.y = a.y + b.y + bb.y;
    r.z = a.z + b.z + bb.z;
    r.w = a.w + b.w + bb.w;
    reinterpret_cast<float4*>(out)[idx] = r;
}

extern "C" void kernel_launch(void* const* d_in, const int* in_sizes, int n_in,
                              void* d_out, int out_size)
{
    const float* x    = (const float*)d_in[0];  // [128, 8192]
    const float* g0   = (const float*)d_in[1];  // [1,32,32,4]
    const float* g1   = (const float*)d_in[2];  // [4,16,16,4]
    const float* g2   = (const float*)d_in[3];  // [4,16,16,1]
    const float* bias = (const float*)d_in[4];  // [8192]
    float* out = (float*)d_out;                 // [128, 8192]

    tt_partial_kernel<<<256, THREADS>>>(x, g0, g1, g2);
    tt_reduce_kernel<<<1024, 256>>>(bias, out);
}